// round 8
// baseline (speedup 1.0000x reference)
#include <cuda_runtime.h>
#include <cstdint>

#define CTC_V  128
#define NEG2   (-1.0e30f)
#define KS     4                 // time steps per barrier (== halo depth)
#define UW     (32 - KS)         // useful lanes per warp (28)
#define NW     10
#define NTHR   (NW * 32)         // 320
#define PSH    280               // shared pair slots (10*28 = 280)
#define PPAD   258
#define TMAX   1024
#define BMAX   64

// Scratch: log2-softmax probs (T*B*V), compact blank probs (B*T), finals.
__device__ float  g_probs[TMAX * BMAX * CTC_V];
__device__ float  g_blank[BMAX * TMAX];
__device__ float2 g_final[BMAX * PPAD];

__device__ __forceinline__ float ex2(float x) {
    float y; asm("ex2.approx.ftz.f32 %0, %1;" : "=f"(y) : "f"(x)); return y;
}
__device__ __forceinline__ float lg2(float x) {
    float y; asm("lg2.approx.ftz.f32 %0, %1;" : "=f"(y) : "f"(x)); return y;
}

// ---------------------------------------------------------------------------
// Kernel 1: log2-softmax over V=128 per (t,b) row; also compact blank stream.
// (Also serves as L2 pre-warmer for the recursion's emit reads.)
// ---------------------------------------------------------------------------
__global__ void softmax_k(const float* __restrict__ acts, int rows, int T, int B) {
    int gw   = (blockIdx.x * blockDim.x + threadIdx.x) >> 5;
    int lane = threadIdx.x & 31;
    if (gw >= rows) return;
    const float L2E = 1.4426950408889634f;
    float4 v = reinterpret_cast<const float4*>(acts)[(size_t)gw * 32 + lane];
    float x0 = v.x * L2E, x1 = v.y * L2E, x2 = v.z * L2E, x3 = v.w * L2E;
    float m = fmaxf(fmaxf(x0, x1), fmaxf(x2, x3));
#pragma unroll
    for (int o = 16; o; o >>= 1) m = fmaxf(m, __shfl_xor_sync(0xffffffffu, m, o));
    float ssum = ex2(x0 - m) + ex2(x1 - m) + ex2(x2 - m) + ex2(x3 - m);
#pragma unroll
    for (int o = 16; o; o >>= 1) ssum += __shfl_xor_sync(0xffffffffu, ssum, o);
    float ls = lg2(ssum) + m;
    reinterpret_cast<float4*>(g_probs)[(size_t)gw * 32 + lane] =
        make_float4(x0 - ls, x1 - ls, x2 - ls, x3 - ls);
    if (lane == 0) {
        int t = gw / B, b = gw - t * B;
        g_blank[b * T + t] = x0 - ls;
    }
}

// ---------------------------------------------------------------------------
// Kernel 2: alpha recursion, log2 domain, pair-per-thread, KS steps per
// barrier with halo lanes. TWO independent batches interleaved per CTA so
// their dependency chains hide each other's MUFU/shfl latency.
// ---------------------------------------------------------------------------
__global__ __launch_bounds__(NTHR, 1) void ctc_alpha2_k(
    const int* __restrict__ labels, const int* __restrict__ act_lens,
    const int* __restrict__ label_lens, int T, int B, int L)
{
    __shared__ __align__(8) float2 shA[2][2][PSH];   // [buf][batch][pair]

    const int V  = CTC_V;
    const int b0 = 2 * blockIdx.x;
    const bool has1 = (b0 + 1 < B);
    const int b1 = has1 ? b0 + 1 : b0;
    const int P  = L + 1;
    const int tid = threadIdx.x, lane = tid & 31, w = tid >> 5;

    int T0 = act_lens[b0]; T0 = T0 > T ? T : (T0 < 1 ? 1 : T0);
    int T1 = act_lens[b1]; T1 = T1 > T ? T : (T1 < 1 ? 1 : T1);
    const int NB0 = (T0 - 1 + KS - 1) / KS;
    const int NB1 = (T1 - 1 + KS - 1) / KS;
    const int NB  = NB0 > NB1 ? NB0 : NB1;

    const int p = w * UW + lane - KS;           // pair index (halo lanes: left dup / <0)
    const bool in0 = ((unsigned)p < (unsigned)P);
    const bool in1 = ((unsigned)p < (unsigned)L);
    const int  la0 = in1 ? labels[b0 * L + p] : 0;
    const int  la1 = in1 ? labels[b1 * L + p] : 0;
    const bool al0 = in1 && (p >= 1) && (la0 != labels[b0 * L + p - 1]);
    const bool al1 = in1 && (p >= 1) && (la1 != labels[b1 * L + p - 1]);
    const bool useful = (lane >= KS) && in0;

    const float* __restrict__ pl0 = g_probs + (size_t)b0 * V + la0;
    const float* __restrict__ pl1 = g_probs + (size_t)b1 * V + la1;
    const float* __restrict__ pb0 = g_blank + (size_t)b0 * T;
    const float* __restrict__ pb1 = g_blank + (size_t)b1 * T;
    const size_t rstr = (size_t)B * V;

    // ---- t = 0 init (registers + shared) ----
    float c00 = NEG2, c01 = NEG2, c10 = NEG2, c11 = NEG2;
    if (p == 0) {
        c00 = __ldg(pb0); c01 = in1 ? __ldg(pl0) : NEG2;
        c10 = __ldg(pb1); c11 = in1 ? __ldg(pl1) : NEG2;
    }
    if (useful) {
        shA[0][0][p] = make_float2(c00, c01);
        shA[0][1][p] = make_float2(c10, c11);
    }

    // emits for block 0 (t = 1..KS), both batches
    float e0b[KS], e0l[KS], e1b[KS], e1l[KS];
#pragma unroll
    for (int j = 0; j < KS; ++j) {
        int t = 1 + j;
        bool ok0 = (t < T0), ok1 = (t < T1);
        e0b[j] = ok0 ? __ldg(pb0 + t) : 0.0f;
        e0l[j] = ok0 ? __ldg(pl0 + (size_t)t * rstr) : 0.0f;
        e1b[j] = ok1 ? __ldg(pb1 + t) : 0.0f;
        e1l[j] = ok1 ? __ldg(pl1 + (size_t)t * rstr) : 0.0f;
    }
    __syncthreads();

    for (int blk = 0; blk < NB; ++blk) {
        // ---- load state at time blk*KS ----
        {
            int pq = p < 0 ? 0 : p;
            float2 v0 = shA[blk & 1][0][pq];
            float2 v1 = shA[blk & 1][1][pq];
            bool ok = (p >= 0) && in0;
            c00 = ok ? v0.x : NEG2; c01 = (ok && in1) ? v0.y : NEG2;
            c10 = ok ? v1.x : NEG2; c11 = (ok && in1) ? v1.y : NEG2;
        }
        // ---- prefetch emits for next block ----
        float n0b[KS], n0l[KS], n1b[KS], n1l[KS];
        {
            int tb = (blk + 1) * KS + 1;
#pragma unroll
            for (int j = 0; j < KS; ++j) {
                int t = tb + j;
                bool ok0 = (t < T0), ok1 = (t < T1);
                n0b[j] = ok0 ? __ldg(pb0 + t) : 0.0f;
                n0l[j] = ok0 ? __ldg(pl0 + (size_t)t * rstr) : 0.0f;
                n1b[j] = ok1 ? __ldg(pb1 + t) : 0.0f;
                n1l[j] = ok1 ? __ldg(pl1 + (size_t)t * rstr) : 0.0f;
            }
        }

        // ---- KS interleaved recursion steps ----
#pragma unroll
        for (int j = 0; j < KS; ++j) {
            int t = blk * KS + 1 + j;
            float z0 = __shfl_up_sync(0xffffffffu, c01, 1);  // both shfls issued up front
            float z1 = __shfl_up_sync(0xffffffffu, c11, 1);

            // batch 0
            {
                float m0 = fmaxf(c00, z0);
                float s0 = m0 + lg2(1.0f + ex2(fminf(c00, z0) - m0)) + e0b[j];
                float q  = al0 ? z0 : NEG2;
                float h  = fmaxf(c01, c00), lo = fminf(c01, c00);
                float m1 = fmaxf(h, q),  l2v = fminf(h, q);
                float s1 = m1 + lg2(1.0f + ex2(lo - m1) + ex2(l2v - m1)) + e0l[j];
                bool u = (t < T0);
                c00 = (u && in0) ? s0 : c00;
                c01 = (u && in1) ? s1 : c01;
            }
            // batch 1
            {
                float m0 = fmaxf(c10, z1);
                float s0 = m0 + lg2(1.0f + ex2(fminf(c10, z1) - m0)) + e1b[j];
                float q  = al1 ? z1 : NEG2;
                float h  = fmaxf(c11, c10), lo = fminf(c11, c10);
                float m1 = fmaxf(h, q),  l2v = fminf(h, q);
                float s1 = m1 + lg2(1.0f + ex2(lo - m1) + ex2(l2v - m1)) + e1l[j];
                bool u = (t < T1);
                c10 = (u && in0) ? s0 : c10;
                c11 = (u && in1) ? s1 : c11;
            }
        }

        if (useful) {
            shA[(blk + 1) & 1][0][p] = make_float2(c00, c01);
            shA[(blk + 1) & 1][1][p] = make_float2(c10, c11);
        }
        __syncthreads();

#pragma unroll
        for (int j = 0; j < KS; ++j) {
            e0b[j] = n0b[j]; e0l[j] = n0l[j];
            e1b[j] = n1b[j]; e1l[j] = n1l[j];
        }
    }

    // final alpha -> global (useful lanes' registers hold final state)
    if (useful) {
        g_final[(size_t)b0 * PPAD + p] = make_float2(c00, c01);
        if (has1) g_final[(size_t)b1 * PPAD + p] = make_float2(c10, c11);
    }
}

// ---------------------------------------------------------------------------
// Kernel 3: per-example cost + deterministic sum.
// ---------------------------------------------------------------------------
__global__ void cost_k(float* out, const int* __restrict__ label_lens, int B, int L) {
    int P = L + 1;
    float sum = 0.0f;
    for (int i = threadIdx.x; i < B; i += 32) {
        int e = label_lens[i]; if (e > P - 1) e = P - 1;
        float2 f0 = g_final[(size_t)i * PPAD + e];
        float a0 = f0.x;
        float a1 = (e >= 1) ? g_final[(size_t)i * PPAD + e - 1].y : NEG2;
        float m = fmaxf(a0, a1);
        sum += -(m + lg2(ex2(a0 - m) + ex2(a1 - m))) * 0.69314718055994530942f;
    }
#pragma unroll
    for (int o = 16; o; o >>= 1) sum += __shfl_xor_sync(0xffffffffu, sum, o);
    if (threadIdx.x == 0) *out = sum;
}

// ---------------------------------------------------------------------------
extern "C" void kernel_launch(void* const* d_in, const int* in_sizes, int n_in,
                              void* d_out, int out_size)
{
    const float* acts      = (const float*)d_in[0];
    const int*   labels    = (const int*)d_in[1];
    const int*   act_lens  = (const int*)d_in[2];
    const int*   label_len = (const int*)d_in[3];

    int B = in_sizes[2];
    int L = in_sizes[1] / B;
    int V = CTC_V;
    int T = in_sizes[0] / (B * V);

    int rows = T * B;
    softmax_k<<<(rows + 7) / 8, 256>>>(acts, rows, T, B);

    int nCTA = (B + 1) / 2;
    ctc_alpha2_k<<<nCTA, NTHR>>>(labels, act_lens, label_len, T, B, L);

    cost_k<<<1, 32>>>((float*)d_out, label_len, B, L);
}

// round 9
// speedup vs baseline: 1.5142x; 1.5142x over previous
#include <cuda_runtime.h>
#include <cstdint>

#define CTC_V  128
#define NEG2   (-1.0e30f)
#define KS     4                 // time steps per barrier (== halo depth)
#define UW     (32 - KS)         // useful lanes per warp (28)
#define NW     10
#define NTHR   (NW * 32)         // 320
#define PPAD   258
#define TMAX   1024
#define BMAX   64

// Scratch: log2-softmax probs (T*B*V), compact blank probs (B*T), finals.
__device__ float  g_probs[TMAX * BMAX * CTC_V];
__device__ float  g_blank[BMAX * TMAX];
__device__ float2 g_final[BMAX * PPAD];

__device__ __forceinline__ float ex2(float x) {
    float y; asm("ex2.approx.ftz.f32 %0, %1;" : "=f"(y) : "f"(x)); return y;
}
__device__ __forceinline__ float lg2(float x) {
    float y; asm("lg2.approx.ftz.f32 %0, %1;" : "=f"(y) : "f"(x)); return y;
}

// ---------------------------------------------------------------------------
// Kernel 1: log2-softmax over V=128 per (t,b) row; also compact blank stream.
// (Also L2 pre-warmer for the recursion's emit reads.)
// ---------------------------------------------------------------------------
__global__ void softmax_k(const float* __restrict__ acts, int rows, int T, int B) {
    int gw   = (blockIdx.x * blockDim.x + threadIdx.x) >> 5;
    int lane = threadIdx.x & 31;
    if (gw >= rows) return;
    const float L2E = 1.4426950408889634f;
    float4 v = reinterpret_cast<const float4*>(acts)[(size_t)gw * 32 + lane];
    float x0 = v.x * L2E, x1 = v.y * L2E, x2 = v.z * L2E, x3 = v.w * L2E;
    float m = fmaxf(fmaxf(x0, x1), fmaxf(x2, x3));
#pragma unroll
    for (int o = 16; o; o >>= 1) m = fmaxf(m, __shfl_xor_sync(0xffffffffu, m, o));
    float ssum = ex2(x0 - m) + ex2(x1 - m) + ex2(x2 - m) + ex2(x3 - m);
#pragma unroll
    for (int o = 16; o; o >>= 1) ssum += __shfl_xor_sync(0xffffffffu, ssum, o);
    float ls = lg2(ssum) + m;
    reinterpret_cast<float4*>(g_probs)[(size_t)gw * 32 + lane] =
        make_float4(x0 - ls, x1 - ls, x2 - ls, x3 - ls);
    if (lane == 0) {
        int t = gw / B, b = gw - t * B;
        g_blank[b * T + t] = x0 - ls;
    }
}

// ---------------------------------------------------------------------------
// Kernel 2: alpha recursion in streaming (M, R) logsumexp form:
//   alpha = M + log2(R),  R in [1, 2) after renorm.
// Update (exact):  M' = max(M_i) + emit;  R' = sum_i R_i * 2^(M_i - max).
// No lg2 in the loop; R renormalized once per block by integer exponent fold.
// One CTA per batch, pair-per-thread, KS steps per barrier with halo lanes.
// ---------------------------------------------------------------------------
__global__ __launch_bounds__(NTHR, 1) void ctc_alpha_k(
    const int* __restrict__ labels, const int* __restrict__ act_lens,
    const int* __restrict__ label_lens, int T, int B, int L)
{
    __shared__ __align__(16) float4 shA[2][NW * UW];   // (M0,R0,M1,R1)

    const int V = CTC_V;
    const int b = blockIdx.x;
    const int P = L + 1;
    const int tid = threadIdx.x, lane = tid & 31, w = tid >> 5;

    int Tlen = act_lens[b];
    if (Tlen > T) Tlen = T;
    if (Tlen < 1) Tlen = 1;

    const int p = w * UW + lane - KS;           // pair index (halo: left dup / <0)
    const bool in0 = ((unsigned)p < (unsigned)P);
    const bool in1 = ((unsigned)p < (unsigned)L);
    const int  lab   = in1 ? labels[b * L + p] : 0;
    const bool allow = in1 && (p >= 1) && (lab != labels[b * L + p - 1]);
    const bool useful = (lane >= KS) && in0;

    const float* __restrict__ pl = g_probs + (size_t)b * V + lab;
    const float* __restrict__ pb = g_blank + (size_t)b * T;
    const size_t rstr = (size_t)B * V;

    // ---- t = 0 init:  M = emit or NEG2, R = 1 ----
    if (useful) {
        float M0 = NEG2, M1 = NEG2;
        if (p == 0) { M0 = __ldg(pb); M1 = in1 ? __ldg(pl) : NEG2; }
        shA[0][p] = make_float4(M0, 1.0f, M1, 1.0f);
    }

    // emits for block 0 (t = 1..KS)
    float eb[KS], el[KS];
#pragma unroll
    for (int j = 0; j < KS; ++j) {
        int t = 1 + j; bool ok = (t < Tlen);
        eb[j] = ok ? __ldg(pb + t) : 0.0f;
        el[j] = ok ? __ldg(pl + (size_t)t * rstr) : 0.0f;
    }
    __syncthreads();

    const int NB = (Tlen - 1 + KS - 1) / KS;
    float M0 = NEG2, R0 = 1.0f, M1 = NEG2, R1 = 1.0f;

    for (int blk = 0; blk < NB; ++blk) {
        // ---- load state at time blk*KS ----
        {
            float4 v = in0 ? shA[blk & 1][p] : make_float4(NEG2, 1.f, NEG2, 1.f);
            M0 = v.x; R0 = v.y;
            M1 = in1 ? v.z : NEG2;
            R1 = in1 ? v.w : 1.0f;
        }
        // ---- prefetch emits for next block ----
        float nb_[KS], nl_[KS];
        {
            int tb = (blk + 1) * KS + 1;
#pragma unroll
            for (int j = 0; j < KS; ++j) {
                int t = tb + j; bool ok = (t < Tlen);
                nb_[j] = ok ? __ldg(pb + t) : 0.0f;
                nl_[j] = ok ? __ldg(pl + (size_t)t * rstr) : 0.0f;
            }
        }

        // ---- KS recursion steps ----
#pragma unroll
        for (int j = 0; j < KS; ++j) {
            int t = blk * KS + 1 + j;
            float Mz = __shfl_up_sync(0xffffffffu, M1, 1);   // left pair's label state
            float Rz = __shfl_up_sync(0xffffffffu, R1, 1);

            // blank: logadd(c0, z) + eb  -> 1 ex2
            float d   = Mz - M0;
            float x   = ex2(0.0f - fabsf(d));
            float big = fmaxf(M0, Mz);
            float Rhi = (d > 0.0f) ? Rz : R0;
            float Rlo = (d > 0.0f) ? R0 : Rz;
            float nM0 = big + eb[j];
            float nR0 = fmaf(Rlo, x, Rhi);

            // label: logadd(c1, c0, allow? z) + el  -> 3 ex2 (parallel)
            float Mq  = allow ? Mz : NEG2;
            float m1  = fmaxf(fmaxf(M1, M0), Mq);
            float nR1 = R1 * ex2(M1 - m1) + R0 * ex2(M0 - m1) + Rz * ex2(Mq - m1);
            float nM1 = m1 + el[j];

            bool u = (t < Tlen);
            M0 = (u && in0) ? nM0 : M0;  R0 = (u && in0) ? nR0 : R0;
            M1 = (u && in1) ? nM1 : M1;  R1 = (u && in1) ? nR1 : R1;
        }

        // ---- renorm R into [1,2) (exact, MUFU-free) and store ----
        {
            int e0 = (int)(__float_as_uint(R0) >> 23) - 127;
            int e1 = (int)(__float_as_uint(R1) >> 23) - 127;
            R0 = __uint_as_float(__float_as_uint(R0) - ((unsigned)e0 << 23));
            R1 = __uint_as_float(__float_as_uint(R1) - ((unsigned)e1 << 23));
            M0 += (float)e0;
            M1 += (float)e1;
        }
        if (useful) shA[(blk + 1) & 1][p] = make_float4(M0, R0, M1, R1);
        __syncthreads();

#pragma unroll
        for (int j = 0; j < KS; ++j) { eb[j] = nb_[j]; el[j] = nl_[j]; }
    }

    // final fold: alpha = M + lg2(R)
    if (useful) {
        float a0 = in0 ? (M0 + lg2(R0)) : NEG2;
        float a1 = in1 ? (M1 + lg2(R1)) : NEG2;
        g_final[(size_t)b * PPAD + p] = make_float2(a0, a1);
    }
}

// ---------------------------------------------------------------------------
// Kernel 3: per-example cost + deterministic sum.
// ---------------------------------------------------------------------------
__global__ void cost_k(float* out, const int* __restrict__ label_lens, int B, int L) {
    int P = L + 1;
    float sum = 0.0f;
    for (int i = threadIdx.x; i < B; i += 32) {
        int e = label_lens[i]; if (e > P - 1) e = P - 1;
        float2 f0 = g_final[(size_t)i * PPAD + e];
        float a0 = f0.x;
        float a1 = (e >= 1) ? g_final[(size_t)i * PPAD + e - 1].y : NEG2;
        float m = fmaxf(a0, a1);
        sum += -(m + lg2(ex2(a0 - m) + ex2(a1 - m))) * 0.69314718055994530942f;
    }
#pragma unroll
    for (int o = 16; o; o >>= 1) sum += __shfl_xor_sync(0xffffffffu, sum, o);
    if (threadIdx.x == 0) *out = sum;
}

// ---------------------------------------------------------------------------
extern "C" void kernel_launch(void* const* d_in, const int* in_sizes, int n_in,
                              void* d_out, int out_size)
{
    const float* acts      = (const float*)d_in[0];
    const int*   labels    = (const int*)d_in[1];
    const int*   act_lens  = (const int*)d_in[2];
    const int*   label_len = (const int*)d_in[3];

    int B = in_sizes[2];
    int L = in_sizes[1] / B;
    int V = CTC_V;
    int T = in_sizes[0] / (B * V);

    int rows = T * B;
    softmax_k<<<(rows + 7) / 8, 256>>>(acts, rows, T, B);

    ctc_alpha_k<<<B, NTHR>>>(labels, act_lens, label_len, T, B, L);

    cost_k<<<1, 32>>>((float*)d_out, label_len, B, L);
}

// round 10
// speedup vs baseline: 2.0409x; 1.3479x over previous
#include <cuda_runtime.h>
#include <cstdint>

#define CTC_V  128
#define NEG2   (-1.0e30f)
#define KS     8                 // time steps per barrier (== halo depth)
#define UW     (32 - KS)         // useful lanes per warp (24)
#define NW     11
#define NTHR   (NW * 32)         // 352
#define PPAD   258
#define TMAX   1024
#define BMAX   64

// Scratch: log2-softmax probs (T*B*V), compact blank probs (B*T), finals.
__device__ float  g_probs[TMAX * BMAX * CTC_V];
__device__ float  g_blank[BMAX * TMAX];
__device__ float2 g_final[BMAX * PPAD];

__device__ __forceinline__ float ex2(float x) {
    float y; asm("ex2.approx.ftz.f32 %0, %1;" : "=f"(y) : "f"(x)); return y;
}
__device__ __forceinline__ float lg2(float x) {
    float y; asm("lg2.approx.ftz.f32 %0, %1;" : "=f"(y) : "f"(x)); return y;
}

// ---------------------------------------------------------------------------
// Kernel 1: log2-softmax over V=128 per (t,b) row; also compact blank stream.
// (Also L2 pre-warmer for the recursion's emit reads.)
// ---------------------------------------------------------------------------
__global__ void softmax_k(const float* __restrict__ acts, int rows, int T, int B) {
    int gw   = (blockIdx.x * blockDim.x + threadIdx.x) >> 5;
    int lane = threadIdx.x & 31;
    if (gw >= rows) return;
    const float L2E = 1.4426950408889634f;
    float4 v = reinterpret_cast<const float4*>(acts)[(size_t)gw * 32 + lane];
    float x0 = v.x * L2E, x1 = v.y * L2E, x2 = v.z * L2E, x3 = v.w * L2E;
    float m = fmaxf(fmaxf(x0, x1), fmaxf(x2, x3));
#pragma unroll
    for (int o = 16; o; o >>= 1) m = fmaxf(m, __shfl_xor_sync(0xffffffffu, m, o));
    float ssum = ex2(x0 - m) + ex2(x1 - m) + ex2(x2 - m) + ex2(x3 - m);
#pragma unroll
    for (int o = 16; o; o >>= 1) ssum += __shfl_xor_sync(0xffffffffu, ssum, o);
    float ls = lg2(ssum) + m;
    reinterpret_cast<float4*>(g_probs)[(size_t)gw * 32 + lane] =
        make_float4(x0 - ls, x1 - ls, x2 - ls, x3 - ls);
    if (lane == 0) {
        int t = gw / B, b = gw - t * B;
        g_blank[b * T + t] = x0 - ls;
    }
}

// ---------------------------------------------------------------------------
// Kernel 2: alpha recursion in streaming (M, R) logsumexp form:
//   alpha = M + log2(R),  R in [1, 2) after per-block renorm.
// Full blocks run with ZERO per-step predication (inactive/halo lanes produce
// finite garbage that nothing consumes; remasked at each block reload).
// The final (possibly partial) block carries the act_len predication.
// ---------------------------------------------------------------------------
__global__ __launch_bounds__(NTHR, 1) void ctc_alpha_k(
    const int* __restrict__ labels, const int* __restrict__ act_lens,
    const int* __restrict__ label_lens, int T, int B, int L)
{
    __shared__ __align__(16) float4 shA[2][NW * UW];   // (M0,R0,M1,R1)

    const int V = CTC_V;
    const int b = blockIdx.x;
    const int P = L + 1;
    const int tid = threadIdx.x, lane = tid & 31, w = tid >> 5;

    int Tlen = act_lens[b];
    if (Tlen > T) Tlen = T;
    if (Tlen < 1) Tlen = 1;

    const int p = w * UW + lane - KS;           // pair index (halo: left dup / <0)
    const bool in0 = ((unsigned)p < (unsigned)P);
    const bool in1 = ((unsigned)p < (unsigned)L);
    const int  lab   = in1 ? labels[b * L + p] : 0;
    const bool allow = in1 && (p >= 1) && (lab != labels[b * L + p - 1]);
    const bool useful = (lane >= KS) && in0;

    const float* __restrict__ pl = g_probs + (size_t)b * V + lab;
    const float* __restrict__ pb = g_blank + (size_t)b * T;
    const size_t rstr = (size_t)B * V;

    // ---- t = 0 init ----
    if (useful) {
        float M0i = NEG2, M1i = NEG2;
        if (p == 0) { M0i = __ldg(pb); M1i = in1 ? __ldg(pl) : NEG2; }
        shA[0][p] = make_float4(M0i, 1.0f, M1i, 1.0f);
    }

    // emits for block 0 (t = 1..KS)
    float eb[KS], el[KS];
#pragma unroll
    for (int j = 0; j < KS; ++j) {
        int t = 1 + j; bool ok = (t < Tlen);
        eb[j] = ok ? __ldg(pb + t) : 0.0f;
        el[j] = ok ? __ldg(pl + (size_t)t * rstr) : 0.0f;
    }
    __syncthreads();

    const int NB     = (Tlen - 1 + KS - 1) / KS;   // total blocks (>= 1 when Tlen > 1)
    const int NBfull = NB > 0 ? NB - 1 : 0;        // last block runs predicated

    float M0 = NEG2, R0 = 1.0f, M1 = NEG2, R1 = 1.0f;

    for (int blk = 0; blk < NB; ++blk) {
        // ---- load state at time blk*KS (masking restores inactive lanes) ----
        {
            float4 v = in0 ? shA[blk & 1][p] : make_float4(NEG2, 1.f, NEG2, 1.f);
            M0 = v.x; R0 = v.y;
            M1 = in1 ? v.z : NEG2;
            R1 = in1 ? v.w : 1.0f;
        }
        // ---- prefetch emits for next block ----
        float nb_[KS], nl_[KS];
        {
            int tb = (blk + 1) * KS + 1;
#pragma unroll
            for (int j = 0; j < KS; ++j) {
                int t = tb + j; bool ok = (t < Tlen);
                nb_[j] = ok ? __ldg(pb + t) : 0.0f;
                nl_[j] = ok ? __ldg(pl + (size_t)t * rstr) : 0.0f;
            }
        }

        if (blk < NBfull) {
            // ---- FULL block: KS steps, no predication ----
#pragma unroll
            for (int j = 0; j < KS; ++j) {
                float Mz = __shfl_up_sync(0xffffffffu, M1, 1);
                float Rz = __shfl_up_sync(0xffffffffu, R1, 1);
                // blank
                float d   = Mz - M0;
                float x   = ex2(0.0f - fabsf(d));
                float Mb  = fmaxf(M0, Mz);
                float Rhi = (d > 0.0f) ? Rz : R0;
                float Rlo = (d > 0.0f) ? R0 : Rz;
                float nM0 = Mb + eb[j];
                float nR0 = fmaf(Rlo, x, Rhi);
                // label
                float Mq  = allow ? Mz : NEG2;
                float m1  = fmaxf(fmaxf(M1, M0), Mq);
                float nR1 = fmaf(R1, ex2(M1 - m1),
                            fmaf(R0, ex2(M0 - m1), Rz * ex2(Mq - m1)));
                M1 = m1 + el[j];  R1 = nR1;
                M0 = nM0;         R0 = nR0;
            }
        } else {
            // ---- TAIL block: predicated on t < Tlen and activity ----
#pragma unroll
            for (int j = 0; j < KS; ++j) {
                int t = blk * KS + 1 + j;
                float Mz = __shfl_up_sync(0xffffffffu, M1, 1);
                float Rz = __shfl_up_sync(0xffffffffu, R1, 1);
                float d   = Mz - M0;
                float x   = ex2(0.0f - fabsf(d));
                float Mb  = fmaxf(M0, Mz);
                float Rhi = (d > 0.0f) ? Rz : R0;
                float Rlo = (d > 0.0f) ? R0 : Rz;
                float nM0 = Mb + eb[j];
                float nR0 = fmaf(Rlo, x, Rhi);
                float Mq  = allow ? Mz : NEG2;
                float m1  = fmaxf(fmaxf(M1, M0), Mq);
                float nR1 = fmaf(R1, ex2(M1 - m1),
                            fmaf(R0, ex2(M0 - m1), Rz * ex2(Mq - m1)));
                float nM1 = m1 + el[j];
                bool u = (t < Tlen);
                M0 = (u && in0) ? nM0 : M0;  R0 = (u && in0) ? nR0 : R0;
                M1 = (u && in1) ? nM1 : M1;  R1 = (u && in1) ? nR1 : R1;
            }
        }

        // ---- renorm R into [1,2) (exact, MUFU-free) and store ----
        {
            int e0 = (int)(__float_as_uint(R0) >> 23) - 127;
            int e1 = (int)(__float_as_uint(R1) >> 23) - 127;
            R0 = __uint_as_float(__float_as_uint(R0) - ((unsigned)e0 << 23));
            R1 = __uint_as_float(__float_as_uint(R1) - ((unsigned)e1 << 23));
            M0 += (float)e0;
            M1 += (float)e1;
        }
        if (useful) shA[(blk + 1) & 1][p] = make_float4(M0, R0, M1, R1);
        __syncthreads();

#pragma unroll
        for (int j = 0; j < KS; ++j) { eb[j] = nb_[j]; el[j] = nl_[j]; }
    }

    // final fold: alpha = M + lg2(R)
    if (useful) {
        float4 v = shA[NB & 1][p];
        float a0 = M0, a1 = M1, r0 = R0, r1 = R1;
        a0 = v.x; r0 = v.y; a1 = v.z; r1 = v.w;
        float f0 = in0 ? (a0 + lg2(r0)) : NEG2;
        float f1 = in1 ? (a1 + lg2(r1)) : NEG2;
        g_final[(size_t)b * PPAD + p] = make_float2(f0, f1);
    }
}

// ---------------------------------------------------------------------------
// Kernel 3: per-example cost + deterministic sum.
// ---------------------------------------------------------------------------
__global__ void cost_k(float* out, const int* __restrict__ label_lens, int B, int L) {
    int P = L + 1;
    float sum = 0.0f;
    for (int i = threadIdx.x; i < B; i += 32) {
        int e = label_lens[i]; if (e > P - 1) e = P - 1;
        float2 f0 = g_final[(size_t)i * PPAD + e];
        float a0 = f0.x;
        float a1 = (e >= 1) ? g_final[(size_t)i * PPAD + e - 1].y : NEG2;
        float m = fmaxf(a0, a1);
        sum += -(m + lg2(ex2(a0 - m) + ex2(a1 - m))) * 0.69314718055994530942f;
    }
#pragma unroll
    for (int o = 16; o; o >>= 1) sum += __shfl_xor_sync(0xffffffffu, sum, o);
    if (threadIdx.x == 0) *out = sum;
}

// ---------------------------------------------------------------------------
extern "C" void kernel_launch(void* const* d_in, const int* in_sizes, int n_in,
                              void* d_out, int out_size)
{
    const float* acts      = (const float*)d_in[0];
    const int*   labels    = (const int*)d_in[1];
    const int*   act_lens  = (const int*)d_in[2];
    const int*   label_len = (const int*)d_in[3];

    int B = in_sizes[2];
    int L = in_sizes[1] / B;
    int V = CTC_V;
    int T = in_sizes[0] / (B * V);

    int rows = T * B;
    softmax_k<<<(rows + 7) / 8, 256>>>(acts, rows, T, B);

    ctc_alpha_k<<<B, NTHR>>>(labels, act_lens, label_len, T, B, L);

    cost_k<<<1, 32>>>((float*)d_out, label_len, B, L);
}

// round 11
// speedup vs baseline: 2.1376x; 1.0473x over previous
#include <cuda_runtime.h>
#include <cstdint>

#define CTC_V  128
#define NEG2   (-1.0e30f)
#define KS     8                 // time steps per barrier (== halo depth)
#define UW     (32 - KS)         // useful lanes per warp (24)
#define NW     11
#define NTHR   (NW * 32)         // 352
#define PPAD   258
#define TMAX   1024
#define BMAX   64

__device__ float  g_probs[TMAX * BMAX * CTC_V];
__device__ float  g_blank[BMAX * TMAX];
__device__ float2 g_final[BMAX * PPAD];

__device__ __forceinline__ float ex2(float x) {
    float y; asm("ex2.approx.ftz.f32 %0, %1;" : "=f"(y) : "f"(x)); return y;
}
__device__ __forceinline__ float lg2(float x) {
    float y; asm("lg2.approx.ftz.f32 %0, %1;" : "=f"(y) : "f"(x)); return y;
}
// Exact renorm: fold R's exponent into M; R -> [1,2). Zero R stays zero.
__device__ __forceinline__ void renorm(float& M, float& R) {
    unsigned u = __float_as_uint(R);
    unsigned eb = u >> 23;
    int e = (eb != 0u) ? (int)eb - 127 : 0;
    R = __uint_as_float(u - ((unsigned)e << 23));
    M += (float)e;
}

// ---------------------------------------------------------------------------
// Kernel 1: log2-softmax, 2 rows per warp (interleaved for MLP/ILP).
// ---------------------------------------------------------------------------
__global__ void softmax_k(const float* __restrict__ acts, int rows, int T, int B) {
    int gw   = (blockIdx.x * blockDim.x + threadIdx.x) >> 5;
    int lane = threadIdx.x & 31;
    int r0 = gw * 2;
    if (r0 >= rows) return;
    int r1 = r0 + 1;                       // rows is even (T*B)
    const float L2E = 1.4426950408889634f;
    float4 va = reinterpret_cast<const float4*>(acts)[(size_t)r0 * 32 + lane];
    float4 vb = reinterpret_cast<const float4*>(acts)[(size_t)r1 * 32 + lane];
    float a0 = va.x * L2E, a1 = va.y * L2E, a2 = va.z * L2E, a3 = va.w * L2E;
    float b0 = vb.x * L2E, b1 = vb.y * L2E, b2 = vb.z * L2E, b3 = vb.w * L2E;
    float ma = fmaxf(fmaxf(a0, a1), fmaxf(a2, a3));
    float mb = fmaxf(fmaxf(b0, b1), fmaxf(b2, b3));
#pragma unroll
    for (int o = 16; o; o >>= 1) {
        ma = fmaxf(ma, __shfl_xor_sync(0xffffffffu, ma, o));
        mb = fmaxf(mb, __shfl_xor_sync(0xffffffffu, mb, o));
    }
    float sa = ex2(a0 - ma) + ex2(a1 - ma) + ex2(a2 - ma) + ex2(a3 - ma);
    float sb = ex2(b0 - mb) + ex2(b1 - mb) + ex2(b2 - mb) + ex2(b3 - mb);
#pragma unroll
    for (int o = 16; o; o >>= 1) {
        sa += __shfl_xor_sync(0xffffffffu, sa, o);
        sb += __shfl_xor_sync(0xffffffffu, sb, o);
    }
    float la = lg2(sa) + ma, lb = lg2(sb) + mb;
    reinterpret_cast<float4*>(g_probs)[(size_t)r0 * 32 + lane] =
        make_float4(a0 - la, a1 - la, a2 - la, a3 - la);
    reinterpret_cast<float4*>(g_probs)[(size_t)r1 * 32 + lane] =
        make_float4(b0 - lb, b1 - lb, b2 - lb, b3 - lb);
    if (lane == 0) {
        int t0 = r0 / B, bb0 = r0 - t0 * B;
        int t1 = r1 / B, bb1 = r1 - t1 * B;
        g_blank[bb0 * T + t0] = a0 - la;
        g_blank[bb1 * T + t1] = b0 - lb;
    }
}

// ---------------------------------------------------------------------------
// Kernel 2: alpha recursion, streaming (M,R) logsumexp, COMMON-MAX step
// (3 ex2/step), per-thread exact renorm every 4 steps. Full blocks run
// unpredicated; tail block carries act_len predication (per-state max form).
// ---------------------------------------------------------------------------
__global__ __launch_bounds__(NTHR, 1) void ctc_alpha_k(
    const int* __restrict__ labels, const int* __restrict__ act_lens,
    const int* __restrict__ label_lens, int T, int B, int L)
{
    __shared__ __align__(16) float4 shA[2][NW * UW];   // (M0,R0,M1,R1)

    const int V = CTC_V;
    const int b = blockIdx.x;
    const int P = L + 1;
    const int tid = threadIdx.x, lane = tid & 31, w = tid >> 5;

    int Tlen = act_lens[b];
    if (Tlen > T) Tlen = T;
    if (Tlen < 1) Tlen = 1;

    const int p = w * UW + lane - KS;
    const bool in0 = ((unsigned)p < (unsigned)P);
    const bool in1 = ((unsigned)p < (unsigned)L);
    const int  lab   = in1 ? labels[b * L + p] : 0;
    const bool allow = in1 && (p >= 1) && (lab != labels[b * L + p - 1]);
    const bool useful = (lane >= KS) && in0;

    const float* __restrict__ pl = g_probs + (size_t)b * V + lab;
    const float* __restrict__ pb = g_blank + (size_t)b * T;
    const size_t rstr = (size_t)B * V;

    if (useful) {
        float M0i = NEG2, M1i = NEG2;
        if (p == 0) { M0i = __ldg(pb); M1i = in1 ? __ldg(pl) : NEG2; }
        shA[0][p] = make_float4(M0i, 1.0f, M1i, 1.0f);
    }

    float eb[KS], el[KS];
#pragma unroll
    for (int j = 0; j < KS; ++j) {
        int t = 1 + j; bool ok = (t < Tlen);
        eb[j] = ok ? __ldg(pb + t) : 0.0f;
        el[j] = ok ? __ldg(pl + (size_t)t * rstr) : 0.0f;
    }
    __syncthreads();

    const int NB     = (Tlen - 1 + KS - 1) / KS;
    const int NBfull = NB > 0 ? NB - 1 : 0;

    float M0 = NEG2, R0 = 1.0f, M1 = NEG2, R1 = 1.0f;

    for (int blk = 0; blk < NB; ++blk) {
        {
            float4 v = in0 ? shA[blk & 1][p] : make_float4(NEG2, 1.f, NEG2, 1.f);
            M0 = v.x; R0 = v.y;
            M1 = in1 ? v.z : NEG2;
            R1 = in1 ? v.w : 1.0f;
        }
        float nb_[KS], nl_[KS];
        {
            int tb = (blk + 1) * KS + 1;
#pragma unroll
            for (int j = 0; j < KS; ++j) {
                int t = tb + j; bool ok = (t < Tlen);
                nb_[j] = ok ? __ldg(pb + t) : 0.0f;
                nl_[j] = ok ? __ldg(pl + (size_t)t * rstr) : 0.0f;
            }
        }

        if (blk < NBfull) {
            // FULL block: common-max steps, no predication; renorm mid+end.
#pragma unroll
            for (int j = 0; j < KS; ++j) {
                float Mz = __shfl_up_sync(0xffffffffu, M1, 1);
                float Rz = __shfl_up_sync(0xffffffffu, R1, 1);
                float mC = fmaxf(fmaxf(M0, M1), Mz);
                float x0 = ex2(M0 - mC);
                float x1 = ex2(M1 - mC);
                float xz = ex2(Mz - mC);
                float R0x0 = R0 * x0;
                float Rzxz = Rz * xz;
                float Rzg  = allow ? Rzxz : 0.0f;
                R0 = R0x0 + Rzxz;
                R1 = fmaf(R1, x1, R0x0 + Rzg);
                M0 = mC + eb[j];
                M1 = mC + el[j];
                if (j == 3) { renorm(M0, R0); renorm(M1, R1); }
            }
            renorm(M0, R0); renorm(M1, R1);
        } else {
            // TAIL block: per-state max, predicated (exactness at boundaries).
#pragma unroll
            for (int j = 0; j < KS; ++j) {
                int t = blk * KS + 1 + j;
                float Mz = __shfl_up_sync(0xffffffffu, M1, 1);
                float Rz = __shfl_up_sync(0xffffffffu, R1, 1);
                float d   = Mz - M0;
                float x   = ex2(0.0f - fabsf(d));
                float Mb  = fmaxf(M0, Mz);
                float Rhi = (d > 0.0f) ? Rz : R0;
                float Rlo = (d > 0.0f) ? R0 : Rz;
                float nM0 = Mb + eb[j];
                float nR0 = fmaf(Rlo, x, Rhi);
                float Mq  = allow ? Mz : NEG2;
                float m1  = fmaxf(fmaxf(M1, M0), Mq);
                float nR1 = fmaf(R1, ex2(M1 - m1),
                            fmaf(R0, ex2(M0 - m1), Rz * ex2(Mq - m1)));
                float nM1 = m1 + el[j];
                bool u = (t < Tlen);
                M0 = (u && in0) ? nM0 : M0;  R0 = (u && in0) ? nR0 : R0;
                M1 = (u && in1) ? nM1 : M1;  R1 = (u && in1) ? nR1 : R1;
            }
            renorm(M0, R0); renorm(M1, R1);
        }

        if (useful) shA[(blk + 1) & 1][p] = make_float4(M0, R0, M1, R1);
        __syncthreads();

#pragma unroll
        for (int j = 0; j < KS; ++j) { eb[j] = nb_[j]; el[j] = nl_[j]; }
    }

    if (useful) {
        float4 v = shA[NB & 1][p];
        float f0 = in0 ? (v.x + lg2(v.y)) : NEG2;
        float f1 = in1 ? (v.z + lg2(v.w)) : NEG2;
        g_final[(size_t)b * PPAD + p] = make_float2(f0, f1);
    }
}

// ---------------------------------------------------------------------------
// Kernel 3: per-example cost + deterministic sum.
// ---------------------------------------------------------------------------
__global__ void cost_k(float* out, const int* __restrict__ label_lens, int B, int L) {
    int P = L + 1;
    float sum = 0.0f;
    for (int i = threadIdx.x; i < B; i += 32) {
        int e = label_lens[i]; if (e > P - 1) e = P - 1;
        float2 f0 = g_final[(size_t)i * PPAD + e];
        float a0 = f0.x;
        float a1 = (e >= 1) ? g_final[(size_t)i * PPAD + e - 1].y : NEG2;
        float m = fmaxf(a0, a1);
        sum += -(m + lg2(ex2(a0 - m) + ex2(a1 - m))) * 0.69314718055994530942f;
    }
#pragma unroll
    for (int o = 16; o; o >>= 1) sum += __shfl_xor_sync(0xffffffffu, sum, o);
    if (threadIdx.x == 0) *out = sum;
}

// ---------------------------------------------------------------------------
extern "C" void kernel_launch(void* const* d_in, const int* in_sizes, int n_in,
                              void* d_out, int out_size)
{
    const float* acts      = (const float*)d_in[0];
    const int*   labels    = (const int*)d_in[1];
    const int*   act_lens  = (const int*)d_in[2];
    const int*   label_len = (const int*)d_in[3];

    int B = in_sizes[2];
    int L = in_sizes[1] / B;
    int V = CTC_V;
    int T = in_sizes[0] / (B * V);

    int rows = T * B;
    int nwarp = (rows + 1) / 2;
    softmax_k<<<(nwarp + 7) / 8, 256>>>(acts, rows, T, B);

    ctc_alpha_k<<<B, NTHR>>>(labels, act_lens, label_len, T, B, L);

    cost_k<<<1, 32>>>((float*)d_out, label_len, B, L);
}

// round 12
// speedup vs baseline: 2.3611x; 1.1046x over previous
#include <cuda_runtime.h>
#include <cstdint>

#define CTC_V  128
#define NEG2   (-1.0e30f)
#define KS     8                 // time steps per barrier (== halo depth)
#define UW     (32 - KS)         // useful lanes per warp (24)
#define NW     11
#define NTHR   (NW * 32)         // 352
#define TMAX   1024
#define BMAX   64
#define TP     (TMAX + KS)       // padded time extent (safe unpredicated prefetch)

// Scratch (padded in t so prefetch never leaves the array).
__device__ float g_probs[TP * BMAX * CTC_V];
__device__ float g_blank[BMAX * TP];

__device__ __forceinline__ float ex2(float x) {
    float y; asm("ex2.approx.ftz.f32 %0, %1;" : "=f"(y) : "f"(x)); return y;
}
__device__ __forceinline__ float lg2(float x) {
    float y; asm("lg2.approx.ftz.f32 %0, %1;" : "=f"(y) : "f"(x)); return y;
}
// Exact renorm: fold R's exponent into M; R -> [1,2). Zero R stays zero.
__device__ __forceinline__ void renorm(float& M, float& R) {
    unsigned u = __float_as_uint(R);
    unsigned eb = u >> 23;
    int e = (eb != 0u) ? (int)eb - 127 : 0;
    R = __uint_as_float(u - ((unsigned)e << 23));
    M += (float)e;
}

// ---------------------------------------------------------------------------
// Kernel 1: log2-softmax, 2 rows per warp (interleaved for MLP/ILP).
// ---------------------------------------------------------------------------
__global__ void softmax_k(const float* __restrict__ acts, int rows, int T, int B) {
    int gw   = (blockIdx.x * blockDim.x + threadIdx.x) >> 5;
    int lane = threadIdx.x & 31;
    int r0 = gw * 2;
    if (r0 >= rows) return;
    int r1 = r0 + 1;                       // rows is even (T*B)
    const float L2E = 1.4426950408889634f;
    float4 va = reinterpret_cast<const float4*>(acts)[(size_t)r0 * 32 + lane];
    float4 vb = reinterpret_cast<const float4*>(acts)[(size_t)r1 * 32 + lane];
    float a0 = va.x * L2E, a1 = va.y * L2E, a2 = va.z * L2E, a3 = va.w * L2E;
    float b0 = vb.x * L2E, b1 = vb.y * L2E, b2 = vb.z * L2E, b3 = vb.w * L2E;
    float ma = fmaxf(fmaxf(a0, a1), fmaxf(a2, a3));
    float mb = fmaxf(fmaxf(b0, b1), fmaxf(b2, b3));
#pragma unroll
    for (int o = 16; o; o >>= 1) {
        ma = fmaxf(ma, __shfl_xor_sync(0xffffffffu, ma, o));
        mb = fmaxf(mb, __shfl_xor_sync(0xffffffffu, mb, o));
    }
    float sa = ex2(a0 - ma) + ex2(a1 - ma) + ex2(a2 - ma) + ex2(a3 - ma);
    float sb = ex2(b0 - mb) + ex2(b1 - mb) + ex2(b2 - mb) + ex2(b3 - mb);
#pragma unroll
    for (int o = 16; o; o >>= 1) {
        sa += __shfl_xor_sync(0xffffffffu, sa, o);
        sb += __shfl_xor_sync(0xffffffffu, sb, o);
    }
    float la = lg2(sa) + ma, lb = lg2(sb) + mb;
    reinterpret_cast<float4*>(g_probs)[(size_t)r0 * 32 + lane] =
        make_float4(a0 - la, a1 - la, a2 - la, a3 - la);
    reinterpret_cast<float4*>(g_probs)[(size_t)r1 * 32 + lane] =
        make_float4(b0 - lb, b1 - lb, b2 - lb, b3 - lb);
    if (lane == 0) {
        int t0 = r0 / B, bb0 = r0 - t0 * B;
        int t1 = r1 / B, bb1 = r1 - t1 * B;
        g_blank[bb0 * TP + t0] = a0 - la;
        g_blank[bb1 * TP + t1] = b0 - lb;
    }
}

// ---------------------------------------------------------------------------
// Kernel 2: alpha recursion, streaming (M,R) logsumexp, common-max step
// (3 ex2/step). Unpredicated full blocks AND unpredicated prefetch (arrays
// padded). Renorm once per block (growth <= 3^KS, exact). Fused final cost
// (atomicAdd into out; out pre-zeroed by memset).
// ---------------------------------------------------------------------------
__global__ __launch_bounds__(NTHR, 1) void ctc_alpha_k(
    float* __restrict__ out,
    const int* __restrict__ labels, const int* __restrict__ act_lens,
    const int* __restrict__ label_lens, int T, int B, int L)
{
    __shared__ __align__(16) float4 shA[2][NW * UW];   // (M0,R0,M1,R1)

    const int V = CTC_V;
    const int b = blockIdx.x;
    const int P = L + 1;
    const int tid = threadIdx.x, lane = tid & 31, w = tid >> 5;

    int Tlen = act_lens[b];
    if (Tlen > T) Tlen = T;
    if (Tlen < 1) Tlen = 1;

    const int p = w * UW + lane - KS;
    const bool in0 = ((unsigned)p < (unsigned)P);
    const bool in1 = ((unsigned)p < (unsigned)L);
    const int  lab   = in1 ? labels[b * L + p] : 0;
    const bool allow = in1 && (p >= 1) && (lab != labels[b * L + p - 1]);
    const bool useful = (lane >= KS) && in0;

    const float* __restrict__ pl = g_probs + (size_t)b * V + lab;
    const float* __restrict__ pb = g_blank + (size_t)b * TP;
    const size_t rstr = (size_t)B * V;

    if (useful) {
        float M0i = NEG2, M1i = NEG2;
        if (p == 0) { M0i = __ldg(pb); M1i = in1 ? __ldg(pl) : NEG2; }
        shA[0][p] = make_float4(M0i, 1.0f, M1i, 1.0f);
    }

    // emits for block 0 (t = 1..KS) — unpredicated (padded arrays)
    float eb[KS], el[KS];
#pragma unroll
    for (int j = 0; j < KS; ++j) {
        int t = 1 + j;
        eb[j] = __ldg(pb + t);
        el[j] = __ldg(pl + (size_t)t * rstr);
    }
    __syncthreads();

    const int NB     = (Tlen - 1 + KS - 1) / KS;
    const int NBfull = NB > 0 ? NB - 1 : 0;

    float M0 = NEG2, R0 = 1.0f, M1 = NEG2, R1 = 1.0f;

    for (int blk = 0; blk < NB; ++blk) {
        {
            float4 v = in0 ? shA[blk & 1][p] : make_float4(NEG2, 1.f, NEG2, 1.f);
            M0 = v.x; R0 = v.y;
            M1 = in1 ? v.z : NEG2;
            R1 = in1 ? v.w : 1.0f;
        }
        // prefetch emits for next block — unpredicated (padded arrays)
        float nb_[KS], nl_[KS];
        {
            int tb = (blk + 1) * KS + 1;
#pragma unroll
            for (int j = 0; j < KS; ++j) {
                int t = tb + j;
                nb_[j] = __ldg(pb + t);
                nl_[j] = __ldg(pl + (size_t)t * rstr);
            }
        }

        if (blk < NBfull) {
            // FULL block: common-max steps, no predication, no mid renorm.
#pragma unroll
            for (int j = 0; j < KS; ++j) {
                float Mz = __shfl_up_sync(0xffffffffu, M1, 1);
                float Rz = __shfl_up_sync(0xffffffffu, R1, 1);
                float mC = fmaxf(fmaxf(M0, M1), Mz);
                float x0 = ex2(M0 - mC);
                float x1 = ex2(M1 - mC);
                float xz = ex2(Mz - mC);
                float R0x0 = R0 * x0;
                float Rzxz = Rz * xz;
                float Rzg  = allow ? Rzxz : 0.0f;
                R0 = R0x0 + Rzxz;
                R1 = fmaf(R1, x1, R0x0 + Rzg);
                M0 = mC + eb[j];
                M1 = mC + el[j];
            }
            renorm(M0, R0); renorm(M1, R1);
        } else {
            // TAIL block: per-state max, predicated (exactness at boundaries).
#pragma unroll
            for (int j = 0; j < KS; ++j) {
                int t = blk * KS + 1 + j;
                float Mz = __shfl_up_sync(0xffffffffu, M1, 1);
                float Rz = __shfl_up_sync(0xffffffffu, R1, 1);
                float d   = Mz - M0;
                float x   = ex2(0.0f - fabsf(d));
                float Mb  = fmaxf(M0, Mz);
                float Rhi = (d > 0.0f) ? Rz : R0;
                float Rlo = (d > 0.0f) ? R0 : Rz;
                float nM0 = Mb + eb[j];
                float nR0 = fmaf(Rlo, x, Rhi);
                float Mq  = allow ? Mz : NEG2;
                float m1  = fmaxf(fmaxf(M1, M0), Mq);
                float nR1 = fmaf(R1, ex2(M1 - m1),
                            fmaf(R0, ex2(M0 - m1), Rz * ex2(Mq - m1)));
                float nM1 = m1 + el[j];
                bool u = (t < Tlen);
                M0 = (u && in0) ? nM0 : M0;  R0 = (u && in0) ? nR0 : R0;
                M1 = (u && in1) ? nM1 : M1;  R1 = (u && in1) ? nR1 : R1;
            }
            renorm(M0, R0); renorm(M1, R1);
        }

        if (useful) shA[(blk + 1) & 1][p] = make_float4(M0, R0, M1, R1);
        __syncthreads();

#pragma unroll
        for (int j = 0; j < KS; ++j) { eb[j] = nb_[j]; el[j] = nl_[j]; }
    }

    // fused cost: alpha_end = blank state of pair e; alpha_end-1 = label
    // state of pair e-1. Both live in the final shared buffer.
    if (tid == 0) {
        int e = label_lens[b]; if (e > P - 1) e = P - 1;
        float4 ve = shA[NB & 1][e];
        float a0 = ve.x + lg2(ve.y);
        float a1 = NEG2;
        if (e >= 1) {
            float4 vp = shA[NB & 1][e - 1];
            a1 = vp.z + lg2(vp.w);
        }
        float m = fmaxf(a0, a1);
        float cost = -(m + lg2(ex2(a0 - m) + ex2(a1 - m))) * 0.69314718055994530942f;
        atomicAdd(out, cost);
    }
}

// ---------------------------------------------------------------------------
extern "C" void kernel_launch(void* const* d_in, const int* in_sizes, int n_in,
                              void* d_out, int out_size)
{
    const float* acts      = (const float*)d_in[0];
    const int*   labels    = (const int*)d_in[1];
    const int*   act_lens  = (const int*)d_in[2];
    const int*   label_len = (const int*)d_in[3];

    int B = in_sizes[2];
    int L = in_sizes[1] / B;
    int V = CTC_V;
    int T = in_sizes[0] / (B * V);

    cudaMemsetAsync(d_out, 0, sizeof(float));

    int rows = T * B;
    int nwarp = (rows + 1) / 2;
    softmax_k<<<(nwarp + 7) / 8, 256>>>(acts, rows, T, B);

    ctc_alpha_k<<<B, NTHR>>>((float*)d_out, labels, act_lens, label_len, T, B, L);
}